// round 4
// baseline (speedup 1.0000x reference)
#include <cuda_runtime.h>
#include <cstdint>

namespace {

constexpr int BATCH     = 20000;
constexpr int MTOT      = 49;
constexpr int KDIM      = 128;
constexpr int NDIM      = 128;
constexpr int TILE_ROWS = 128;
constexpr int NTHREADS  = 256;

constexpr int CHUNK   = 16384;           // bytes: 128 rows x 32 k x 4B
constexpr int W_OFF   = 2 * CHUNK;       // A double buffer first
constexpr int SMEM_TOTAL = W_OFF + 4 * CHUNK;   // 32KB A + 64KB W = 98304 B

// smem layout (per operand plane): [ksg][row][32B], where within the 32B row
// the 8 k-values of group ksg are permuted as k' = 2*t + khalf  (k = khalf*4 + t).
// 1-bit swizzle: byte offset bit4 ^= (row>>2)&1 -> conflict-free STS.128 & LDS.64.

__device__ __forceinline__ uint32_t smem_u32(const void* p) {
    uint32_t a;
    asm("{ .reg .u64 t; cvta.to.shared.u64 t, %1; cvt.u32.u64 %0, t; }"
        : "=r"(a) : "l"(p));
    return a;
}

__device__ __forceinline__ uint32_t cvt_tf32(float x) {
    uint32_t r;
    asm("cvt.rna.tf32.f32 %0, %1;" : "=r"(r) : "f"(x));
    return r;
}

__device__ __forceinline__ void sts128(uint32_t addr, uint32_t a, uint32_t b,
                                       uint32_t c, uint32_t d) {
    asm volatile("st.shared.v4.b32 [%0], {%1, %2, %3, %4};"
                 :: "r"(addr), "r"(a), "r"(b), "r"(c), "r"(d) : "memory");
}

__device__ __forceinline__ void lds64(uint32_t& x, uint32_t& y, uint32_t addr) {
    asm volatile("ld.shared.v2.b32 {%0, %1}, [%2];"
                 : "=r"(x), "=r"(y) : "r"(addr));
}

__device__ __forceinline__ void mma_tf32(float* c, uint32_t a0, uint32_t a1,
                                         uint32_t a2, uint32_t a3,
                                         uint32_t b0, uint32_t b1) {
    asm volatile(
        "mma.sync.aligned.m16n8k8.row.col.f32.tf32.tf32.f32 "
        "{%0,%1,%2,%3}, {%4,%5,%6,%7}, {%8,%9}, {%0,%1,%2,%3};"
        : "+f"(c[0]), "+f"(c[1]), "+f"(c[2]), "+f"(c[3])
        : "r"(a0), "r"(a1), "r"(a2), "r"(a3), "r"(b0), "r"(b1));
}

__global__ void __launch_bounds__(NTHREADS, 2)
so3_linear_kernel(const float* __restrict__ in,
                  const float* __restrict__ w,
                  const float* __restrict__ bias,
                  float* __restrict__ out)
{
    extern __shared__ char smem[];
    const uint32_t sb = smem_u32(smem);

    const int tid  = threadIdx.x;
    const int lane = tid & 31;
    const int wid  = tid >> 5;
    const int g    = lane >> 2;
    const int t    = lane & 3;

    const int m       = blockIdx.y;
    const int rowBase = blockIdx.x * TILE_ROWS;

    int l = 0;
    while ((l + 1) * (l + 1) <= m) l++;
    const float* wl = w + (size_t)l * NDIM * KDIM;

    // ---- producer mapping: thread -> (row rr, k-half kd) ----
    const int rr = tid & 127;
    const int kd = tid >> 7;                 // 0: k 0..15 of chunk, 1: k 16..31
    const uint32_t swz = (uint32_t)(((rr >> 2) & 1) << 4);
    const uint32_t u0 = 0u ^ swz, u1 = 16u ^ swz;

    int b = rowBase + rr;
    if (b >= BATCH) b = BATCH - 1;           // clamped rows never stored
    const float* ap = in + ((size_t)b * MTOT + m) * KDIM + kd * 16;

    const uint32_t aStsRow = sb + (uint32_t)(kd * 2 * 4096 + rr * 32);

    // ---- prologue: issue A chunk0 loads ----
    float4 A0[4], A1[4];
    #pragma unroll
    for (int i = 0; i < 4; i++)
        A0[i] = *reinterpret_cast<const float4*>(ap + i * 4);

    // ---- W: load entire 128x128 block once, cvt+permute+swizzle into smem ----
    {
        const float* wp = wl + (size_t)rr * KDIM + kd * 64;
        const uint32_t wSts = sb + (uint32_t)(W_OFF + kd * 8 * 4096 + rr * 32);
        #pragma unroll
        for (int h = 0; h < 8; h++) {
            float4 q0 = *reinterpret_cast<const float4*>(wp + h * 8);
            float4 q1 = *reinterpret_cast<const float4*>(wp + h * 8 + 4);
            sts128(wSts + h * 4096 + u0,
                   cvt_tf32(q0.x), cvt_tf32(q1.x), cvt_tf32(q0.y), cvt_tf32(q1.y));
            sts128(wSts + h * 4096 + u1,
                   cvt_tf32(q0.z), cvt_tf32(q1.z), cvt_tf32(q0.w), cvt_tf32(q1.w));
        }
    }

    // ---- STS A chunk0, prefetch chunk1 into A1 ----
    #pragma unroll
    for (int h = 0; h < 2; h++) {
        float4 q0 = A0[2 * h], q1 = A0[2 * h + 1];
        sts128(aStsRow + h * 4096 + u0,
               cvt_tf32(q0.x), cvt_tf32(q1.x), cvt_tf32(q0.y), cvt_tf32(q1.y));
        sts128(aStsRow + h * 4096 + u1,
               cvt_tf32(q0.z), cvt_tf32(q1.z), cvt_tf32(q0.w), cvt_tf32(q1.w));
    }
    #pragma unroll
    for (int i = 0; i < 4; i++)
        A1[i] = *reinterpret_cast<const float4*>(ap + 32 + i * 4);

    __syncthreads();

    // ---- consumer mapping ----
    const int warp_row = (wid & 3) * 32;
    const int warp_col = (wid >> 2) * 64;
    const uint32_t xo = (uint32_t)(t * 8) ^ (uint32_t)(((g >> 2) & 1) << 4);

    float acc[2][8][4] = {};

    #pragma unroll
    for (int c = 0; c < 4; c++) {
        const uint32_t Ab = sb + (uint32_t)((c & 1) * CHUNK) + xo;
        const uint32_t Wb = sb + (uint32_t)(W_OFF + c * CHUNK) + xo;

        #pragma unroll
        for (int ks = 0; ks < 4; ks++) {
            const uint32_t As = Ab + (uint32_t)(ks * 4096);
            const uint32_t Ws = Wb + (uint32_t)(ks * 4096);

            uint32_t af[2][4];
            #pragma unroll
            for (int mi = 0; mi < 2; mi++) {
                const uint32_t r = (uint32_t)(warp_row + mi * 16 + g);
                lds64(af[mi][0], af[mi][2], As + r * 32);          // row r   : (kh0, kh1)
                lds64(af[mi][1], af[mi][3], As + (r + 8) * 32);    // row r+8 : (kh0, kh1)
            }
            #pragma unroll
            for (int ni = 0; ni < 8; ni++) {
                const uint32_t cc = (uint32_t)(warp_col + ni * 8 + g);
                uint32_t b0, b1;
                lds64(b0, b1, Ws + cc * 32);
                mma_tf32(acc[0][ni], af[0][0], af[0][1], af[0][2], af[0][3], b0, b1);
                mma_tf32(acc[1][ni], af[1][0], af[1][1], af[1][2], af[1][3], b0, b1);
            }
        }

        if (c < 3) {
            // Register rotation: chunk c+1 lives in A1 when c is even, A0 when
            // c is odd (prologue: A0=chunk0, A1=chunk1; each iter loads c+2
            // into the set freed by the STS of chunk c, i.e. the other set).
            float4* dst = (c & 1) ? A0 : A1;       // holds chunk c+1 -> STS now
            float4* nxt = (c & 1) ? A1 : A0;       // already consumed -> refill
            if (c < 2) {
                #pragma unroll
                for (int i = 0; i < 4; i++)
                    nxt[i] = *reinterpret_cast<const float4*>(ap + (c + 2) * 32 + i * 4);
            }
            // STS chunk c+1 (into buffer retired at chunk c-1)
            const uint32_t ab = aStsRow + (uint32_t)(((c + 1) & 1) * CHUNK);
            #pragma unroll
            for (int h = 0; h < 2; h++) {
                float4 q0 = dst[2 * h], q1 = dst[2 * h + 1];
                sts128(ab + h * 4096 + u0,
                       cvt_tf32(q0.x), cvt_tf32(q1.x), cvt_tf32(q0.y), cvt_tf32(q1.y));
                sts128(ab + h * 4096 + u1,
                       cvt_tf32(q0.z), cvt_tf32(q1.z), cvt_tf32(q0.w), cvt_tf32(q1.w));
            }
            __syncthreads();
        }
    }

    // ---- epilogue ----
    const bool addb = (m == 0);
    #pragma unroll
    for (int mi = 0; mi < 2; mi++) {
        #pragma unroll
        for (int ni = 0; ni < 8; ni++) {
            const int cc = warp_col + ni * 8 + 2 * t;
            const int r0 = rowBase + warp_row + mi * 16 + g;
            float2 v0 = make_float2(acc[mi][ni][0], acc[mi][ni][1]);
            float2 v1 = make_float2(acc[mi][ni][2], acc[mi][ni][3]);
            if (addb) {
                const float b0v = bias[cc], b1v = bias[cc + 1];
                v0.x += b0v; v0.y += b1v;
                v1.x += b0v; v1.y += b1v;
            }
            if (r0 < BATCH)
                *reinterpret_cast<float2*>(out + (((size_t)r0 * MTOT + m) * NDIM + cc)) = v0;
            if (r0 + 8 < BATCH)
                *reinterpret_cast<float2*>(out + (((size_t)(r0 + 8) * MTOT + m) * NDIM + cc)) = v1;
        }
    }
}

}  // namespace

extern "C" void kernel_launch(void* const* d_in, const int* in_sizes, int n_in,
                              void* d_out, int out_size) {
    (void)in_sizes; (void)n_in; (void)out_size;
    const float* in   = (const float*)d_in[0];
    const float* w    = (const float*)d_in[1];
    const float* bias = (const float*)d_in[2];
    float* out        = (float*)d_out;

    cudaFuncSetAttribute(so3_linear_kernel,
                         cudaFuncAttributeMaxDynamicSharedMemorySize, SMEM_TOTAL);

    dim3 grid((BATCH + TILE_ROWS - 1) / TILE_ROWS, MTOT);
    so3_linear_kernel<<<grid, NTHREADS, SMEM_TOTAL>>>(in, w, bias, out);
}

// round 5
// speedup vs baseline: 1.5090x; 1.5090x over previous
#include <cuda_runtime.h>
#include <cstdint>

namespace {

constexpr int BATCH     = 20000;
constexpr int MTOT      = 49;
constexpr int KDIM      = 128;
constexpr int NDIM      = 128;
constexpr int TILE_ROWS = 128;
constexpr int NTHREADS  = 256;

constexpr int CHUNK      = 16384;                 // 128 rows x 128B (32 tf32 k)
constexpr int W_OFF      = 2 * CHUNK;             // A double buffer first
constexpr int SMEM_TOTAL = W_OFF + 4 * CHUNK;     // 32KB A + 64KB W = 98304 B

// SW128 K-major atom: smem row = 128B = 32 k values; swizzle o ^= ((o>>3)&0x70).
// Producer stores 16B segs; consumer uses ldmatrix.m8n8.x4.b16 (tf32 tile viewed
// as b16: 8x8 tf32 tile == two side-by-side 8x8 b16 tiles).

__device__ __forceinline__ uint32_t smem_u32(const void* p) {
    uint32_t a;
    asm("{ .reg .u64 t; cvta.to.shared.u64 t, %1; cvt.u32.u64 %0, t; }"
        : "=r"(a) : "l"(p));
    return a;
}

__device__ __forceinline__ uint32_t cvt_tf32(float x) {
    uint32_t r;
    asm("cvt.rna.tf32.f32 %0, %1;" : "=r"(r) : "f"(x));
    return r;
}

__device__ __forceinline__ void sts128(uint32_t addr, uint32_t a, uint32_t b,
                                       uint32_t c, uint32_t d) {
    asm volatile("st.shared.v4.b32 [%0], {%1, %2, %3, %4};"
                 :: "r"(addr), "r"(a), "r"(b), "r"(c), "r"(d) : "memory");
}

__device__ __forceinline__ void ldsm4(uint32_t& r0, uint32_t& r1,
                                      uint32_t& r2, uint32_t& r3, uint32_t addr) {
    asm volatile("ldmatrix.sync.aligned.m8n8.x4.shared.b16 {%0,%1,%2,%3}, [%4];"
                 : "=r"(r0), "=r"(r1), "=r"(r2), "=r"(r3) : "r"(addr));
}

__device__ __forceinline__ void mma_tf32(float* c, uint32_t a0, uint32_t a1,
                                         uint32_t a2, uint32_t a3,
                                         uint32_t b0, uint32_t b1) {
    asm volatile(
        "mma.sync.aligned.m16n8k8.row.col.f32.tf32.tf32.f32 "
        "{%0,%1,%2,%3}, {%4,%5,%6,%7}, {%8,%9}, {%0,%1,%2,%3};"
        : "+f"(c[0]), "+f"(c[1]), "+f"(c[2]), "+f"(c[3])
        : "r"(a0), "r"(a1), "r"(a2), "r"(a3), "r"(b0), "r"(b1));
}

__global__ void __launch_bounds__(NTHREADS, 2)
so3_linear_kernel(const float* __restrict__ in,
                  const float* __restrict__ w,
                  const float* __restrict__ bias,
                  float* __restrict__ out)
{
    extern __shared__ char smem[];
    const uint32_t sb = smem_u32(smem);

    const int tid  = threadIdx.x;
    const int lane = tid & 31;
    const int wid  = tid >> 5;
    const int g    = lane >> 2;
    const int t    = lane & 3;

    const int m       = blockIdx.y;
    const int rowBase = blockIdx.x * TILE_ROWS;

    int l = 0;
    while ((l + 1) * (l + 1) <= m) l++;
    const float* wl = w + (size_t)l * NDIM * KDIM;

    // ---- producer mapping: 8 threads per row cover 128B (fully coalesced) ----
    const int prow = tid >> 3;               // 0..31 (+32*i)
    const int seg  = tid & 7;                // 16B segment within 128B row
    const uint32_t stsOff0 =
        (uint32_t)(prow * 128 + ((seg ^ (prow & 7)) << 4));  // +i*4096 per row block

    int b0r = rowBase + prow;                // A rows handled by this thread
    const float* aRow[4];
    #pragma unroll
    for (int i = 0; i < 4; i++) {
        int b = b0r + 32 * i;
        if (b >= BATCH) b = BATCH - 1;       // clamped rows never stored
        aRow[i] = in + ((size_t)b * MTOT + m) * KDIM + seg * 4;
    }
    const float* wRow0 = wl + (size_t)prow * KDIM + seg * 4;   // +i*32*KDIM

    // ---- prologue: A chunk0 loads ----
    float4 A0[4], A1[4];
    #pragma unroll
    for (int i = 0; i < 4; i++)
        A0[i] = *reinterpret_cast<const float4*>(aRow[i]);

    // ---- stage W once: 4 planes of [128 rows x 32 k] ----
    #pragma unroll
    for (int p = 0; p < 4; p++) {
        float4 q[4];
        #pragma unroll
        for (int i = 0; i < 4; i++)
            q[i] = *reinterpret_cast<const float4*>(wRow0 + i * (32 * KDIM) + p * 32);
        const uint32_t wb = sb + (uint32_t)(W_OFF + p * CHUNK) + stsOff0;
        #pragma unroll
        for (int i = 0; i < 4; i++)
            sts128(wb + i * 4096, cvt_tf32(q[i].x), cvt_tf32(q[i].y),
                                  cvt_tf32(q[i].z), cvt_tf32(q[i].w));
    }

    // ---- STS A chunk0, prefetch chunk1 into A1 ----
    {
        const uint32_t ab = sb + stsOff0;
        #pragma unroll
        for (int i = 0; i < 4; i++)
            sts128(ab + i * 4096, cvt_tf32(A0[i].x), cvt_tf32(A0[i].y),
                                  cvt_tf32(A0[i].z), cvt_tf32(A0[i].w));
    }
    #pragma unroll
    for (int i = 0; i < 4; i++)
        A1[i] = *reinterpret_cast<const float4*>(aRow[i] + 32);

    __syncthreads();

    // ---- consumer mapping ----
    const int warp_row = (wid & 3) * 32;
    const int warp_col = (wid >> 2) * 64;
    const int x7 = lane & 7;

    // ldmatrix lane roles (x4: lanes 0-7 tile0 rows, 8-15 tile1, 16-23 tile2, 24-31 tile3)
    // A tiles: {rows R..R+7, segL}, {R+8..R+15, segL}, {R.., segL+1}, {R+8.., segL+1}
    const int aRowOff = ((lane >> 3) & 1) * 8 + x7;
    const int aSh     = lane >> 4;                    // 0/1 -> k-half seg
    // B tiles: {n C..C+7, segL}, {C.., segL+1}, {C+8.., segL}, {C+8.., segL+1}
    const int bRowOff = ((lane >> 4) & 1) * 8 + x7;
    const int bSh     = (lane >> 3) & 1;

    const uint32_t aBaseOff = (uint32_t)((warp_row + aRowOff) * 128);
    const uint32_t bBaseOff = (uint32_t)((warp_col + bRowOff) * 128);
    uint32_t aSegT[4], bSegT[4];
    #pragma unroll
    for (int ks = 0; ks < 4; ks++) {
        aSegT[ks] = (uint32_t)(((2 * ks + aSh) ^ x7) << 4);
        bSegT[ks] = (uint32_t)(((2 * ks + bSh) ^ x7) << 4);
    }

    float acc[2][8][4] = {};

    #pragma unroll
    for (int c = 0; c < 4; c++) {
        const uint32_t Ab = sb + (uint32_t)((c & 1) * CHUNK) + aBaseOff;
        const uint32_t Wb = sb + (uint32_t)(W_OFF + c * CHUNK) + bBaseOff;

        #pragma unroll
        for (int ks = 0; ks < 4; ks++) {
            uint32_t af[4], ag[4];
            ldsm4(af[0], af[1], af[2], af[3], Ab + aSegT[ks]);          // mi=0
            ldsm4(ag[0], ag[1], ag[2], ag[3], Ab + 2048 + aSegT[ks]);   // mi=1 (+16 rows)

            #pragma unroll
            for (int np = 0; np < 4; np++) {
                uint32_t b0, b1, b2, b3;   // (b0,b1)=ni 2np, (b2,b3)=ni 2np+1
                ldsm4(b0, b1, b2, b3, Wb + (uint32_t)(np * 2048) + bSegT[ks]);
                mma_tf32(acc[0][2 * np],     af[0], af[1], af[2], af[3], b0, b1);
                mma_tf32(acc[0][2 * np + 1], af[0], af[1], af[2], af[3], b2, b3);
                mma_tf32(acc[1][2 * np],     ag[0], ag[1], ag[2], ag[3], b0, b1);
                mma_tf32(acc[1][2 * np + 1], ag[0], ag[1], ag[2], ag[3], b2, b3);
            }
        }

        if (c < 3) {
            // rotation: chunk c+1 is in A1 when c even, A0 when c odd
            float4* dst = (c & 1) ? A0 : A1;   // holds chunk c+1 -> STS now
            float4* nxt = (c & 1) ? A1 : A0;   // consumed -> refill with c+2
            if (c < 2) {
                #pragma unroll
                for (int i = 0; i < 4; i++)
                    nxt[i] = *reinterpret_cast<const float4*>(aRow[i] + (c + 2) * 32);
            }
            const uint32_t ab = sb + (uint32_t)(((c + 1) & 1) * CHUNK) + stsOff0;
            #pragma unroll
            for (int i = 0; i < 4; i++)
                sts128(ab + i * 4096, cvt_tf32(dst[i].x), cvt_tf32(dst[i].y),
                                      cvt_tf32(dst[i].z), cvt_tf32(dst[i].w));
            __syncthreads();
        }
    }

    // ---- epilogue ----
    const bool addb = (m == 0);
    #pragma unroll
    for (int mi = 0; mi < 2; mi++) {
        #pragma unroll
        for (int ni = 0; ni < 8; ni++) {
            const int cc = warp_col + ni * 8 + 2 * t;
            const int r0 = rowBase + warp_row + mi * 16 + g;
            float2 v0 = make_float2(acc[mi][ni][0], acc[mi][ni][1]);
            float2 v1 = make_float2(acc[mi][ni][2], acc[mi][ni][3]);
            if (addb) {
                const float b0v = bias[cc], b1v = bias[cc + 1];
                v0.x += b0v; v0.y += b1v;
                v1.x += b0v; v1.y += b1v;
            }
            if (r0 < BATCH)
                *reinterpret_cast<float2*>(out + (((size_t)r0 * MTOT + m) * NDIM + cc)) = v0;
            if (r0 + 8 < BATCH)
                *reinterpret_cast<float2*>(out + (((size_t)(r0 + 8) * MTOT + m) * NDIM + cc)) = v1;
        }
    }
}

}  // namespace

extern "C" void kernel_launch(void* const* d_in, const int* in_sizes, int n_in,
                              void* d_out, int out_size) {
    (void)in_sizes; (void)n_in; (void)out_size;
    const float* in   = (const float*)d_in[0];
    const float* w    = (const float*)d_in[1];
    const float* bias = (const float*)d_in[2];
    float* out        = (float*)d_out;

    cudaFuncSetAttribute(so3_linear_kernel,
                         cudaFuncAttributeMaxDynamicSharedMemorySize, SMEM_TOTAL);

    dim3 grid((BATCH + TILE_ROWS - 1) / TILE_ROWS, MTOT);
    so3_linear_kernel<<<grid, NTHREADS, SMEM_TOTAL>>>(in, w, bias, out);
}

// round 6
// speedup vs baseline: 1.8638x; 1.2351x over previous
#include <cuda_runtime.h>
#include <cstdint>

namespace {

constexpr int BATCH     = 20000;
constexpr int MTOT      = 49;
constexpr int KDIM      = 128;
constexpr int NDIM      = 128;
constexpr int TILE_ROWS = 128;
constexpr int NTHREADS  = 256;

constexpr int CHUNK      = 16384;                 // 128 rows x 128B (32 fp32 k)
constexpr int W_OFF      = 2 * CHUNK;             // A double buffer first
constexpr int SMEM_TOTAL = W_OFF + 4 * CHUNK;     // 32KB A + 64KB W = 98304 B

// SW128 K-major atom: smem row = 128B; swizzle seg ^= row&7 (16B granules).
// A stored as RAW fp32 via cp.async (mma.tf32 truncates in HW); W cvt.rna at stage.

__device__ __forceinline__ uint32_t smem_u32(const void* p) {
    uint32_t a;
    asm("{ .reg .u64 t; cvta.to.shared.u64 t, %1; cvt.u32.u64 %0, t; }"
        : "=r"(a) : "l"(p));
    return a;
}

__device__ __forceinline__ uint32_t cvt_tf32(float x) {
    uint32_t r;
    asm("cvt.rna.tf32.f32 %0, %1;" : "=r"(r) : "f"(x));
    return r;
}

__device__ __forceinline__ void cp16(uint32_t dst, const void* src) {
    asm volatile("cp.async.cg.shared.global [%0], [%1], 16;"
                 :: "r"(dst), "l"(src));
}

__device__ __forceinline__ void sts128(uint32_t addr, uint32_t a, uint32_t b,
                                       uint32_t c, uint32_t d) {
    asm volatile("st.shared.v4.b32 [%0], {%1, %2, %3, %4};"
                 :: "r"(addr), "r"(a), "r"(b), "r"(c), "r"(d) : "memory");
}

__device__ __forceinline__ void ldsm4(uint32_t& r0, uint32_t& r1,
                                      uint32_t& r2, uint32_t& r3, uint32_t addr) {
    asm volatile("ldmatrix.sync.aligned.m8n8.x4.shared.b16 {%0,%1,%2,%3}, [%4];"
                 : "=r"(r0), "=r"(r1), "=r"(r2), "=r"(r3) : "r"(addr));
}

__device__ __forceinline__ void mma_tf32(float* c, uint32_t a0, uint32_t a1,
                                         uint32_t a2, uint32_t a3,
                                         uint32_t b0, uint32_t b1) {
    asm volatile(
        "mma.sync.aligned.m16n8k8.row.col.f32.tf32.tf32.f32 "
        "{%0,%1,%2,%3}, {%4,%5,%6,%7}, {%8,%9}, {%0,%1,%2,%3};"
        : "+f"(c[0]), "+f"(c[1]), "+f"(c[2]), "+f"(c[3])
        : "r"(a0), "r"(a1), "r"(a2), "r"(a3), "r"(b0), "r"(b1));
}

__global__ void __launch_bounds__(NTHREADS, 2)
so3_linear_kernel(const float* __restrict__ in,
                  const float* __restrict__ w,
                  const float* __restrict__ bias,
                  float* __restrict__ out)
{
    extern __shared__ char smem[];
    const uint32_t sb = smem_u32(smem);

    const int tid  = threadIdx.x;
    const int lane = tid & 31;
    const int wid  = tid >> 5;
    const int g    = lane >> 2;
    const int t    = lane & 3;

    const int m = blockIdx.y;
    int l = 0;
    while ((l + 1) * (l + 1) <= m) l++;
    const float* wl = w + (size_t)l * NDIM * KDIM;

    // ---- producer mapping ----
    const int prow = tid >> 3;
    const int seg  = tid & 7;
    const uint32_t stsOff0 = (uint32_t)(prow * 128 + ((seg ^ (prow & 7)) << 4));

    const int rowBase0 = blockIdx.x * (2 * TILE_ROWS);
    const int rowBase1 = rowBase0 + TILE_ROWS;
    const bool valid1  = rowBase1 < BATCH;

    const float* aR[2][4];
    #pragma unroll
    for (int tl = 0; tl < 2; tl++) {
        const int rb = tl ? rowBase1 : rowBase0;
        #pragma unroll
        for (int i = 0; i < 4; i++) {
            int b = rb + prow + 32 * i;
            if (b >= BATCH) b = BATCH - 1;       // clamped rows never stored
            aR[tl][i] = in + ((size_t)b * MTOT + m) * KDIM + seg * 4;
        }
    }

    auto issueChunk = [&](const float* const* ar, int c, int buf) {
        const uint32_t ad = sb + (uint32_t)(buf * CHUNK) + stsOff0;
        #pragma unroll
        for (int i = 0; i < 4; i++)
            cp16(ad + i * 4096, ar[i] + c * 32);
        asm volatile("cp.async.commit_group;");
    };

    // issue tile0 chunk0 first: DRAM latency hides under W staging
    issueChunk(aR[0], 0, 0);

    // ---- stage W once (cvt.rna) ----
    {
        const float* wRow0 = wl + (size_t)prow * KDIM + seg * 4;
        #pragma unroll
        for (int p = 0; p < 4; p++) {
            float4 q[4];
            #pragma unroll
            for (int i = 0; i < 4; i++)
                q[i] = *reinterpret_cast<const float4*>(wRow0 + i * (32 * KDIM) + p * 32);
            const uint32_t wb = sb + (uint32_t)(W_OFF + p * CHUNK) + stsOff0;
            #pragma unroll
            for (int i = 0; i < 4; i++)
                sts128(wb + i * 4096, cvt_tf32(q[i].x), cvt_tf32(q[i].y),
                                      cvt_tf32(q[i].z), cvt_tf32(q[i].w));
        }
    }

    // ---- consumer mapping (validated in R5) ----
    const int warp_row = (wid & 3) * 32;
    const int warp_col = (wid >> 2) * 64;
    const int x7 = lane & 7;
    const int aRowOff = ((lane >> 3) & 1) * 8 + x7;
    const int aSh     = lane >> 4;
    const int bRowOff = ((lane >> 4) & 1) * 8 + x7;
    const int bSh     = (lane >> 3) & 1;
    const uint32_t aBaseOff = (uint32_t)((warp_row + aRowOff) * 128);
    const uint32_t bBaseOff = (uint32_t)((warp_col + bRowOff) * 128);
    uint32_t aSegT[4], bSegT[4];
    #pragma unroll
    for (int ks = 0; ks < 4; ks++) {
        aSegT[ks] = (uint32_t)(((2 * ks + aSh) ^ x7) << 4);
        bSegT[ks] = (uint32_t)(((2 * ks + bSh) ^ x7) << 4);
    }

    float acc[2][8][4] = {};
    const bool addb = (m == 0);

    #pragma unroll
    for (int tl = 0; tl < 2; tl++) {
        if (tl == 1 && !valid1) break;

        #pragma unroll
        for (int c = 0; c < 4; c++) {
            asm volatile("cp.async.wait_group 0;");
            __syncthreads();

            // issue next chunk into the buffer consumed 1 iteration ago
            if (c < 3)
                issueChunk(aR[tl], c + 1, (c + 1) & 1);
            else if (tl == 0 && valid1)
                issueChunk(aR[1], 0, 0);

            const uint32_t Ab = sb + (uint32_t)((c & 1) * CHUNK) + aBaseOff;
            const uint32_t Wb = sb + (uint32_t)(W_OFF + c * CHUNK) + bBaseOff;

            #pragma unroll
            for (int ks = 0; ks < 4; ks++) {
                uint32_t af[4], ag[4];
                ldsm4(af[0], af[1], af[2], af[3], Ab + aSegT[ks]);
                ldsm4(ag[0], ag[1], ag[2], ag[3], Ab + 2048 + aSegT[ks]);
                #pragma unroll
                for (int np = 0; np < 4; np++) {
                    uint32_t b0, b1, b2, b3;
                    ldsm4(b0, b1, b2, b3, Wb + (uint32_t)(np * 2048) + bSegT[ks]);
                    mma_tf32(acc[0][2 * np],     af[0], af[1], af[2], af[3], b0, b1);
                    mma_tf32(acc[0][2 * np + 1], af[0], af[1], af[2], af[3], b2, b3);
                    mma_tf32(acc[1][2 * np],     ag[0], ag[1], ag[2], ag[3], b0, b1);
                    mma_tf32(acc[1][2 * np + 1], ag[0], ag[1], ag[2], ag[3], b2, b3);
                }
            }
        }

        // ---- epilogue (overlaps next tile's chunk0 cp.async) ----
        const int rb = tl ? rowBase1 : rowBase0;
        #pragma unroll
        for (int mi = 0; mi < 2; mi++) {
            #pragma unroll
            for (int ni = 0; ni < 8; ni++) {
                const int cc = warp_col + ni * 8 + 2 * t;
                const int r0 = rb + warp_row + mi * 16 + g;
                float2 v0 = make_float2(acc[mi][ni][0], acc[mi][ni][1]);
                float2 v1 = make_float2(acc[mi][ni][2], acc[mi][ni][3]);
                if (addb) {
                    const float b0v = bias[cc], b1v = bias[cc + 1];
                    v0.x += b0v; v0.y += b1v;
                    v1.x += b0v; v1.y += b1v;
                }
                if (r0 < BATCH)
                    *reinterpret_cast<float2*>(out + (((size_t)r0 * MTOT + m) * NDIM + cc)) = v0;
                if (r0 + 8 < BATCH)
                    *reinterpret_cast<float2*>(out + (((size_t)(r0 + 8) * MTOT + m) * NDIM + cc)) = v1;
                acc[mi][ni][0] = 0.f; acc[mi][ni][1] = 0.f;
                acc[mi][ni][2] = 0.f; acc[mi][ni][3] = 0.f;
            }
        }
    }
}

}  // namespace

extern "C" void kernel_launch(void* const* d_in, const int* in_sizes, int n_in,
                              void* d_out, int out_size) {
    (void)in_sizes; (void)n_in; (void)out_size;
    const float* in   = (const float*)d_in[0];
    const float* w    = (const float*)d_in[1];
    const float* bias = (const float*)d_in[2];
    float* out        = (float*)d_out;

    cudaFuncSetAttribute(so3_linear_kernel,
                         cudaFuncAttributeMaxDynamicSharedMemorySize, SMEM_TOTAL);

    dim3 grid((BATCH + 2 * TILE_ROWS - 1) / (2 * TILE_ROWS), MTOT);
    so3_linear_kernel<<<grid, NTHREADS, SMEM_TOTAL>>>(in, w, bias, out);
}

// round 7
// speedup vs baseline: 1.8937x; 1.0160x over previous
#include <cuda_runtime.h>
#include <cstdint>

namespace {

constexpr int BATCH     = 20000;
constexpr int MTOT      = 49;
constexpr int KDIM      = 128;
constexpr int NDIM      = 128;
constexpr int TILE_ROWS = 128;
constexpr int NTILES    = 4;                      // row-tiles per CTA
constexpr int NTHREADS  = 256;

constexpr int CHUNK      = 16384;                 // 128 rows x 128B (32 fp32 k)
constexpr int W_OFF      = 3 * CHUNK;             // A triple buffer first
constexpr int SMEM_TOTAL = W_OFF + 4 * CHUNK;     // 48KB A + 64KB W = 114688 B

constexpr size_t ROW_STRIDE   = (size_t)MTOT * KDIM;         // floats per batch row
constexpr size_t TILE_STRIDE  = (size_t)TILE_ROWS * ROW_STRIDE;
constexpr size_t ROW32_STRIDE = (size_t)32 * ROW_STRIDE;

// SW128 K-major atom: smem row = 128B; swizzle seg ^= row&7 (16B granules).
// A raw fp32 via cp.async (mma.tf32 truncates in HW); W cvt.rna at stage time.

__device__ __forceinline__ uint32_t smem_u32(const void* p) {
    uint32_t a;
    asm("{ .reg .u64 t; cvta.to.shared.u64 t, %1; cvt.u32.u64 %0, t; }"
        : "=r"(a) : "l"(p));
    return a;
}

__device__ __forceinline__ uint32_t cvt_tf32(float x) {
    uint32_t r;
    asm("cvt.rna.tf32.f32 %0, %1;" : "=r"(r) : "f"(x));
    return r;
}

__device__ __forceinline__ void cp16z(uint32_t dst, const void* src, int srcsize) {
    asm volatile("cp.async.cg.shared.global [%0], [%1], 16, %2;"
                 :: "r"(dst), "l"(src), "r"(srcsize));
}

__device__ __forceinline__ void sts128(uint32_t addr, uint32_t a, uint32_t b,
                                       uint32_t c, uint32_t d) {
    asm volatile("st.shared.v4.b32 [%0], {%1, %2, %3, %4};"
                 :: "r"(addr), "r"(a), "r"(b), "r"(c), "r"(d) : "memory");
}

__device__ __forceinline__ void ldsm4(uint32_t& r0, uint32_t& r1,
                                      uint32_t& r2, uint32_t& r3, uint32_t addr) {
    asm volatile("ldmatrix.sync.aligned.m8n8.x4.shared.b16 {%0,%1,%2,%3}, [%4];"
                 : "=r"(r0), "=r"(r1), "=r"(r2), "=r"(r3) : "r"(addr));
}

__device__ __forceinline__ void mma_tf32(float* c, uint32_t a0, uint32_t a1,
                                         uint32_t a2, uint32_t a3,
                                         uint32_t b0, uint32_t b1) {
    asm volatile(
        "mma.sync.aligned.m16n8k8.row.col.f32.tf32.tf32.f32 "
        "{%0,%1,%2,%3}, {%4,%5,%6,%7}, {%8,%9}, {%0,%1,%2,%3};"
        : "+f"(c[0]), "+f"(c[1]), "+f"(c[2]), "+f"(c[3])
        : "r"(a0), "r"(a1), "r"(a2), "r"(a3), "r"(b0), "r"(b1));
}

__global__ void __launch_bounds__(NTHREADS, 2)
so3_linear_kernel(const float* __restrict__ in,
                  const float* __restrict__ w,
                  const float* __restrict__ bias,
                  float* __restrict__ out)
{
    extern __shared__ char smem[];
    const uint32_t sb = smem_u32(smem);

    const int tid  = threadIdx.x;
    const int lane = tid & 31;
    const int wid  = tid >> 5;
    const int g    = lane >> 2;
    const int t    = lane & 3;

    const int m = blockIdx.y;
    int l = 0;
    while ((l + 1) * (l + 1) <= m) l++;
    const float* wl = w + (size_t)l * NDIM * KDIM;

    // ---- producer mapping ----
    const int prow = tid >> 3;
    const int seg  = tid & 7;
    const uint32_t stsOff0 = (uint32_t)(prow * 128 + ((seg ^ (prow & 7)) << 4));

    const int rowBase0 = blockIdx.x * (NTILES * TILE_ROWS);
    const int nt = min(NTILES, (BATCH - rowBase0 + TILE_ROWS - 1) / TILE_ROWS);
    const int nchunks = nt * 4;

    const int bRow0 = rowBase0 + prow;
    const float* aBase = in + ((size_t)bRow0 * MTOT + m) * KDIM + seg * 4;

    auto issueChunk = [&](int gj) {
        if (gj < nchunks) {
            const int tl = gj >> 2, c = gj & 3;
            const uint32_t ad = sb + (uint32_t)((gj % 3) * CHUNK) + stsOff0;
            const float* base = aBase + (size_t)tl * TILE_STRIDE + c * 32;
            #pragma unroll
            for (int i = 0; i < 4; i++) {
                const int ok = (bRow0 + tl * TILE_ROWS + 32 * i) < BATCH ? 16 : 0;
                cp16z(ad + i * 4096, base + i * ROW32_STRIDE, ok);
            }
        }
        asm volatile("cp.async.commit_group;");
    };

    // prologue: 2 chunks in flight before W staging hides their latency
    issueChunk(0);
    issueChunk(1);

    // ---- stage W once (cvt.rna) ----
    {
        const float* wRow0 = wl + (size_t)prow * KDIM + seg * 4;
        #pragma unroll
        for (int p = 0; p < 4; p++) {
            float4 q[4];
            #pragma unroll
            for (int i = 0; i < 4; i++)
                q[i] = *reinterpret_cast<const float4*>(wRow0 + i * (32 * KDIM) + p * 32);
            const uint32_t wb = sb + (uint32_t)(W_OFF + p * CHUNK) + stsOff0;
            #pragma unroll
            for (int i = 0; i < 4; i++)
                sts128(wb + i * 4096, cvt_tf32(q[i].x), cvt_tf32(q[i].y),
                                      cvt_tf32(q[i].z), cvt_tf32(q[i].w));
        }
    }

    // ---- consumer mapping (validated R5/R6) ----
    const int warp_row = (wid & 3) * 32;
    const int warp_col = (wid >> 2) * 64;
    const int x7 = lane & 7;
    const int aRowOff = ((lane >> 3) & 1) * 8 + x7;
    const int aSh     = lane >> 4;
    const int bRowOff = ((lane >> 4) & 1) * 8 + x7;
    const int bSh     = (lane >> 3) & 1;
    const uint32_t aBaseOff = (uint32_t)((warp_row + aRowOff) * 128);
    const uint32_t bBaseOff = (uint32_t)((warp_col + bRowOff) * 128);
    uint32_t aSegT[4], bSegT[4];
    #pragma unroll
    for (int ks = 0; ks < 4; ks++) {
        aSegT[ks] = (uint32_t)(((2 * ks + aSh) ^ x7) << 4);
        bSegT[ks] = (uint32_t)(((2 * ks + bSh) ^ x7) << 4);
    }

    float acc[2][8][4] = {};
    const bool addb = (m == 0);

    for (int tl = 0; tl < nt; tl++) {
        #pragma unroll
        for (int c = 0; c < 4; c++) {
            const int gj = tl * 4 + c;
            asm volatile("cp.async.wait_group 1;");
            __syncthreads();
            issueChunk(gj + 2);

            const uint32_t Ab = sb + (uint32_t)((gj % 3) * CHUNK) + aBaseOff;
            const uint32_t Wb = sb + (uint32_t)(W_OFF + c * CHUNK) + bBaseOff;

            #pragma unroll
            for (int ks = 0; ks < 4; ks++) {
                uint32_t af[4], ag[4];
                ldsm4(af[0], af[1], af[2], af[3], Ab + aSegT[ks]);
                ldsm4(ag[0], ag[1], ag[2], ag[3], Ab + 2048 + aSegT[ks]);
                #pragma unroll
                for (int np = 0; np < 4; np++) {
                    uint32_t b0, b1, b2, b3;
                    ldsm4(b0, b1, b2, b3, Wb + (uint32_t)(np * 2048) + bSegT[ks]);
                    mma_tf32(acc[0][2 * np],     af[0], af[1], af[2], af[3], b0, b1);
                    mma_tf32(acc[0][2 * np + 1], af[0], af[1], af[2], af[3], b2, b3);
                    mma_tf32(acc[1][2 * np],     ag[0], ag[1], ag[2], ag[3], b0, b1);
                    mma_tf32(acc[1][2 * np + 1], ag[0], ag[1], ag[2], ag[3], b2, b3);
                }
            }
        }

        // ---- epilogue tile tl (overlaps next tile's in-flight loads) ----
        const int rb = rowBase0 + tl * TILE_ROWS;
        #pragma unroll
        for (int mi = 0; mi < 2; mi++) {
            #pragma unroll
            for (int ni = 0; ni < 8; ni++) {
                const int cc = warp_col + ni * 8 + 2 * t;
                const int r0 = rb + warp_row + mi * 16 + g;
                float2 v0 = make_float2(acc[mi][ni][0], acc[mi][ni][1]);
                float2 v1 = make_float2(acc[mi][ni][2], acc[mi][ni][3]);
                if (addb) {
                    const float b0v = bias[cc], b1v = bias[cc + 1];
                    v0.x += b0v; v0.y += b1v;
                    v1.x += b0v; v1.y += b1v;
                }
                if (r0 < BATCH)
                    *reinterpret_cast<float2*>(out + (((size_t)r0 * MTOT + m) * NDIM + cc)) = v0;
                if (r0 + 8 < BATCH)
                    *reinterpret_cast<float2*>(out + (((size_t)(r0 + 8) * MTOT + m) * NDIM + cc)) = v1;
                acc[mi][ni][0] = 0.f; acc[mi][ni][1] = 0.f;
                acc[mi][ni][2] = 0.f; acc[mi][ni][3] = 0.f;
            }
        }
    }
}

}  // namespace

extern "C" void kernel_launch(void* const* d_in, const int* in_sizes, int n_in,
                              void* d_out, int out_size) {
    (void)in_sizes; (void)n_in; (void)out_size;
    const float* in   = (const float*)d_in[0];
    const float* w    = (const float*)d_in[1];
    const float* bias = (const float*)d_in[2];
    float* out        = (float*)d_out;

    cudaFuncSetAttribute(so3_linear_kernel,
                         cudaFuncAttributeMaxDynamicSharedMemorySize, SMEM_TOTAL);

    dim3 grid((BATCH + NTILES * TILE_ROWS - 1) / (NTILES * TILE_ROWS), MTOT);
    so3_linear_kernel<<<grid, NTHREADS, SMEM_TOTAL>>>(in, w, bias, out);
}

// round 8
// speedup vs baseline: 2.1314x; 1.1255x over previous
#include <cuda_runtime.h>
#include <cstdint>

namespace {

constexpr int BATCH     = 20000;
constexpr int MTOT      = 49;
constexpr int KDIM      = 128;
constexpr int NDIM      = 128;
constexpr int TILE_ROWS = 128;
constexpr int NTILES    = 4;                      // row-tiles per CTA
constexpr int NTHREADS  = 256;

constexpr int CHUNK      = 16384;                 // 128 rows x 128B = 64 fp16 k
constexpr int W_OFF      = 3 * CHUNK;             // A triple-buffer ring first
constexpr int SMEM_TOTAL = W_OFF + 2 * CHUNK;     // 48KB A + 32KB W = 81920 B

constexpr size_t ROW_STRIDE = (size_t)MTOT * KDIM;   // floats between batch rows

// SW128-style layout: smem row = 128B (64 fp16 k-values), 8 x 16B segs,
// seg' = seg ^ (row & 7). Consumer: ldmatrix.m8n8.x4.b16 -> m16n8k16 fp16 mma.

__device__ __forceinline__ uint32_t smem_u32(const void* p) {
    uint32_t a;
    asm("{ .reg .u64 t; cvta.to.shared.u64 t, %1; cvt.u32.u64 %0, t; }"
        : "=r"(a) : "l"(p));
    return a;
}

__device__ __forceinline__ uint32_t f16x2(float lo, float hi) {
    uint32_t r;                    // low half = lo (lower k index)
    asm("cvt.rn.f16x2.f32 %0, %2, %1;" : "=r"(r) : "f"(lo), "f"(hi));
    return r;
}

__device__ __forceinline__ void sts128(uint32_t addr, uint32_t a, uint32_t b,
                                       uint32_t c, uint32_t d) {
    asm volatile("st.shared.v4.b32 [%0], {%1, %2, %3, %4};"
                 :: "r"(addr), "r"(a), "r"(b), "r"(c), "r"(d) : "memory");
}

__device__ __forceinline__ void ldsm4(uint32_t& r0, uint32_t& r1,
                                      uint32_t& r2, uint32_t& r3, uint32_t addr) {
    asm volatile("ldmatrix.sync.aligned.m8n8.x4.shared.b16 {%0,%1,%2,%3}, [%4];"
                 : "=r"(r0), "=r"(r1), "=r"(r2), "=r"(r3) : "r"(addr));
}

__device__ __forceinline__ void mma_f16(float* c, uint32_t a0, uint32_t a1,
                                        uint32_t a2, uint32_t a3,
                                        uint32_t b0, uint32_t b1) {
    asm volatile(
        "mma.sync.aligned.m16n8k16.row.col.f32.f16.f16.f32 "
        "{%0,%1,%2,%3}, {%4,%5,%6,%7}, {%8,%9}, {%0,%1,%2,%3};"
        : "+f"(c[0]), "+f"(c[1]), "+f"(c[2]), "+f"(c[3])
        : "r"(a0), "r"(a1), "r"(a2), "r"(a3), "r"(b0), "r"(b1));
}

__global__ void __launch_bounds__(NTHREADS, 2)
so3_linear_kernel(const float* __restrict__ in,
                  const float* __restrict__ w,
                  const float* __restrict__ bias,
                  float* __restrict__ out)
{
    extern __shared__ char smem[];
    const uint32_t sb = smem_u32(smem);

    const int tid  = threadIdx.x;
    const int lane = tid & 31;
    const int wid  = tid >> 5;
    const int g    = lane >> 2;
    const int t    = lane & 3;

    const int m = blockIdx.y;
    int l = 0;
    while ((l + 1) * (l + 1) <= m) l++;
    const float* wl = w + (size_t)l * NDIM * KDIM;

    // ---- producer mapping: 8 threads/row, 16B fp16 (= 8 k) per thread ----
    const int prow = tid >> 3;               // 0..31 (+32*i covers 128 rows)
    const int seg  = tid & 7;
    const uint32_t stsOff0 = (uint32_t)(prow * 128 + ((seg ^ (prow & 7)) << 4));

    const int rowBase0 = blockIdx.x * (NTILES * TILE_ROWS);
    const int nt = min(NTILES, (BATCH - rowBase0 + TILE_ROWS - 1) / TILE_ROWS);
    const int nchunks = nt * 2;              // k64 chunks per tile

    const float* aCol = in + (size_t)m * KDIM + seg * 8;

    float st[4][8];                           // staged fp32 for one chunk

    auto ldgChunk = [&](int gj) {
        const int tl = gj >> 1, c = gj & 1;
        #pragma unroll
        for (int i = 0; i < 4; i++) {
            int r = rowBase0 + tl * TILE_ROWS + prow + 32 * i;
            if (r >= BATCH) r = BATCH - 1;   // clamped rows never stored
            const float* p = aCol + (size_t)r * ROW_STRIDE + c * 64;
            float4 q0 = *reinterpret_cast<const float4*>(p);
            float4 q1 = *reinterpret_cast<const float4*>(p + 4);
            st[i][0] = q0.x; st[i][1] = q0.y; st[i][2] = q0.z; st[i][3] = q0.w;
            st[i][4] = q1.x; st[i][5] = q1.y; st[i][6] = q1.z; st[i][7] = q1.w;
        }
    };
    auto stsChunk = [&](int gj) {
        const uint32_t ad = sb + (uint32_t)((gj % 3) * CHUNK) + stsOff0;
        #pragma unroll
        for (int i = 0; i < 4; i++)
            sts128(ad + i * 4096,
                   f16x2(st[i][0], st[i][1]), f16x2(st[i][2], st[i][3]),
                   f16x2(st[i][4], st[i][5]), f16x2(st[i][6], st[i][7]));
    };

    // ---- prologue: chunk0 staged, chunk1 in regs, W staged ----
    ldgChunk(0);
    stsChunk(0);
    ldgChunk(1);

    {   // W: 128 n-rows x 128 k fp16, 2 planes of k64
        const float* wRow = wl + (size_t)prow * KDIM + seg * 8;
        #pragma unroll
        for (int p = 0; p < 2; p++) {
            const uint32_t wb = sb + (uint32_t)(W_OFF + p * CHUNK) + stsOff0;
            #pragma unroll
            for (int i = 0; i < 4; i++) {
                const float* q = wRow + i * (32 * KDIM) + p * 64;
                float4 q0 = *reinterpret_cast<const float4*>(q);
                float4 q1 = *reinterpret_cast<const float4*>(q + 4);
                sts128(wb + i * 4096,
                       f16x2(q0.x, q0.y), f16x2(q0.z, q0.w),
                       f16x2(q1.x, q1.y), f16x2(q1.z, q1.w));
            }
        }
    }
    __syncthreads();

    // ---- consumer mapping (validated R5-R7; k16 steps now) ----
    const int warp_row = (wid & 3) * 32;
    const int warp_col = (wid >> 2) * 64;
    const int x7 = lane & 7;
    const int aRowOff = ((lane >> 3) & 1) * 8 + x7;
    const int aSh     = lane >> 4;
    const int bRowOff = ((lane >> 4) & 1) * 8 + x7;
    const int bSh     = (lane >> 3) & 1;
    const uint32_t aBaseOff = (uint32_t)((warp_row + aRowOff) * 128);
    const uint32_t bBaseOff = (uint32_t)((warp_col + bRowOff) * 128);
    uint32_t aSegT[4], bSegT[4];
    #pragma unroll
    for (int ks = 0; ks < 4; ks++) {
        aSegT[ks] = (uint32_t)(((2 * ks + aSh) ^ x7) << 4);
        bSegT[ks] = (uint32_t)(((2 * ks + bSh) ^ x7) << 4);
    }

    float acc[2][8][4] = {};
    const bool addb = (m == 0);

    for (int gj = 0; gj < nchunks; gj++) {
        const int c = gj & 1;

        if (gj + 1 < nchunks) stsChunk(gj + 1);        // buffer free (2 syncs ago)
        if (gj + 2 < nchunks) ldgChunk(gj + 2);        // latency hidden by consume

        const uint32_t Ab = sb + (uint32_t)((gj % 3) * CHUNK) + aBaseOff;
        const uint32_t Wb = sb + (uint32_t)(W_OFF + c * CHUNK) + bBaseOff;

        #pragma unroll
        for (int ks = 0; ks < 4; ks++) {               // 4 x k16 = k64
            uint32_t af[4], ag[4];
            ldsm4(af[0], af[1], af[2], af[3], Ab + aSegT[ks]);
            ldsm4(ag[0], ag[1], ag[2], ag[3], Ab + 2048 + aSegT[ks]);
            #pragma unroll
            for (int np = 0; np < 4; np++) {
                uint32_t b0, b1, b2, b3;
                ldsm4(b0, b1, b2, b3, Wb + (uint32_t)(np * 2048) + bSegT[ks]);
                mma_f16(acc[0][2 * np],     af[0], af[1], af[2], af[3], b0, b1);
                mma_f16(acc[0][2 * np + 1], af[0], af[1], af[2], af[3], b2, b3);
                mma_f16(acc[1][2 * np],     ag[0], ag[1], ag[2], ag[3], b0, b1);
                mma_f16(acc[1][2 * np + 1], ag[0], ag[1], ag[2], ag[3], b2, b3);
            }
        }
        __syncthreads();

        if (c == 1) {
            // ---- epilogue for tile gj>>1 ----
            const int rb = rowBase0 + (gj >> 1) * TILE_ROWS;
            #pragma unroll
            for (int mi = 0; mi < 2; mi++) {
                #pragma unroll
                for (int ni = 0; ni < 8; ni++) {
                    const int cc = warp_col + ni * 8 + 2 * t;
                    const int r0 = rb + warp_row + mi * 16 + g;
                    float2 v0 = make_float2(acc[mi][ni][0], acc[mi][ni][1]);
                    float2 v1 = make_float2(acc[mi][ni][2], acc[mi][ni][3]);
                    if (addb) {
                        const float b0v = bias[cc], b1v = bias[cc + 1];
                        v0.x += b0v; v0.y += b1v;
                        v1.x += b0v; v1.y += b1v;
                    }
                    if (r0 < BATCH)
                        *reinterpret_cast<float2*>(out + (((size_t)r0 * MTOT + m) * NDIM + cc)) = v0;
                    if (r0 + 8 < BATCH)
                        *reinterpret_cast<float2*>(out + (((size_t)(r0 + 8) * MTOT + m) * NDIM + cc)) = v1;
                    acc[mi][ni][0] = 0.f; acc[mi][ni][1] = 0.f;
                    acc[mi][ni][2] = 0.f; acc[mi][ni][3] = 0.f;
                }
            }
        }
    }
}

}  // namespace

extern "C" void kernel_launch(void* const* d_in, const int* in_sizes, int n_in,
                              void* d_out, int out_size) {
    (void)in_sizes; (void)n_in; (void)out_size;
    const float* in   = (const float*)d_in[0];
    const float* w    = (const float*)d_in[1];
    const float* bias = (const float*)d_in[2];
    float* out        = (float*)d_out;

    cudaFuncSetAttribute(so3_linear_kernel,
                         cudaFuncAttributeMaxDynamicSharedMemorySize, SMEM_TOTAL);

    dim3 grid((BATCH + NTILES * TILE_ROWS - 1) / (NTILES * TILE_ROWS), MTOT);
    so3_linear_kernel<<<grid, NTHREADS, SMEM_TOTAL>>>(in, w, bias, out);
}